// round 13
// baseline (speedup 1.0000x reference)
#include <cuda_runtime.h>
#include <cuda_bf16.h>

#define N_NODES 100000
#define N_EDGES 3200000
#define H 32
#define NB_SCAN ((N_NODES + 1023) / 1024)   // 98 blocks of 1024 for prefix scan
#define NODE_GRID 1024                      // persistent-block grid for node kernels
#define TBSZ 256
#define NWARP (TBSZ / 32)

// Scratch (device globals; no dynamic allocation allowed).
__device__ float    g_hA[N_NODES * H];
__device__ float    g_hB[N_NODES * H];
__device__ int      g_deg[N_NODES];
__device__ int      g_off[N_NODES];         // block-local exclusive prefix (final = + g_part[n>>10])
__device__ int      g_part[NB_SCAN];        // per-scan-block exclusive base
__device__ int      g_scnt;
__device__ uint2    g_smeta[N_EDGES];       // staging: (src | rank<<17, dst | flags<<30)
__device__ float4   g_sattr[N_EDGES];       // staging: edge_attr row
__device__ unsigned g_meta[N_EDGES];        // CSR payload: src | flags<<30
__device__ float4   g_attr[N_EDGES];        // CSR payload: edge_attr row

__device__ __forceinline__ float warp_sum(float v) {
    #pragma unroll
    for (int o = 16; o > 0; o >>= 1) v += __shfl_xor_sync(0xffffffffu, v, o);
    return v;
}

// Packed f32x2 helpers (Blackwell FFMA2/ADD2 path).
__device__ __forceinline__ unsigned long long pack2(float lo, float hi) {
    unsigned long long r;
    asm("mov.b64 %0, {%1, %2};" : "=l"(r) : "f"(lo), "f"(hi));
    return r;
}
__device__ __forceinline__ void unpack2(unsigned long long v, float& lo, float& hi) {
    asm("mov.b64 {%0, %1}, %2;" : "=f"(lo), "=f"(hi) : "l"(v));
}
__device__ __forceinline__ void ffma2(unsigned long long& acc,
                                      unsigned long long a, unsigned long long b) {
    asm("fma.rn.f32x2 %0, %1, %2, %3;" : "=l"(acc) : "l"(a), "l"(b), "l"(acc));
}
__device__ __forceinline__ unsigned long long add2(unsigned long long a,
                                                   unsigned long long b) {
    unsigned long long r;
    asm("add.rn.f32x2 %0, %1, %2;" : "=l"(r) : "l"(a), "l"(b));
    return r;
}

// Joint (sum, sumsq) butterfly reduction on packed f32x2.
__device__ __forceinline__ unsigned long long warp_sum2(unsigned long long p) {
    #pragma unroll
    for (int o = 16; o > 0; o >>= 1)
        p = add2(p, __shfl_xor_sync(0xffffffffu, p, o));
    return p;
}

// ---------------------------------------------------------------------------
// Init: h = relu(concat(aa_emb[aa], atom_emb[at]) @ W1 + b1) @ W2 + b2.
// Block-persistent; also zeroes g_deg and g_scnt (merged launch).
// ---------------------------------------------------------------------------
__global__ void k_init(const int* __restrict__ aa_idx, const int* __restrict__ atom_idx,
                       const float* __restrict__ aa_emb, const float* __restrict__ atom_emb,
                       const float* __restrict__ W1, const float* __restrict__ b1,
                       const float* __restrict__ W2, const float* __restrict__ b2) {
    __shared__ float sW1[H * H], sW2[H * H], sb1[H], sb2[H];
    int tid = threadIdx.x;
    if (blockIdx.x == 0 && tid == 0) g_scnt = 0;
    for (int i = tid; i < H * H; i += blockDim.x) { sW1[i] = W1[i]; sW2[i] = W2[i]; }
    if (tid < H) { sb1[tid] = b1[tid]; sb2[tid] = b2[tid]; }
    __syncthreads();

    int lane    = tid & 31;
    int warp0   = (blockIdx.x * blockDim.x + tid) >> 5;
    int n_warps = (NODE_GRID * TBSZ) >> 5;

    for (int n = warp0; n < N_NODES; n += n_warps) {
        if (lane == 0) g_deg[n] = 0;

        int aa = aa_idx[n];
        int at = atom_idx[n];
        float x = (lane < 16) ? aa_emb[aa * 16 + lane] : atom_emb[at * 16 + (lane - 16)];

        float t = sb1[lane];
        #pragma unroll
        for (int j = 0; j < H; j++) t = fmaf(__shfl_sync(0xffffffffu, x, j), sW1[j * H + lane], t);
        t = fmaxf(t, 0.f);

        float o = sb2[lane];
        #pragma unroll
        for (int j = 0; j < H; j++) o = fmaf(__shfl_sync(0xffffffffu, t, j), sW2[j * H + lane], o);

        g_hA[n * H + lane] = o;
    }
}

// ---------------------------------------------------------------------------
// CSR build, step 1: masks (layer-invariant, computed ONCE), dst histogram
// (atomicAdd return value = within-dst rank -> no second atomic pass),
// warp-aggregated append to staging.
// ---------------------------------------------------------------------------
__global__ void k_hist(const int* __restrict__ ei, const float* __restrict__ ea,
                       const int* __restrict__ atom_idx) {
    int e = blockIdx.x * blockDim.x + threadIdx.x;
    unsigned flags = 0;
    int src = 0, dst = 0, rank = 0;
    float4 a = make_float4(0.f, 0.f, 0.f, 0.f);
    if (e < N_EDGES) {
        src = ei[e];
        dst = ei[N_EDGES + e];
        a   = reinterpret_cast<const float4*>(ea)[e];
        float dist = a.x;
        bool sm = (dist >= 0.f) && (dist < 10.f);
        bool lm = (dist >= 0.f) && (dist <= 25.f);
        if (lm) lm = (atom_idx[src] == 1) && (atom_idx[dst] == 1);
        flags = (sm ? 1u : 0u) | (lm ? 2u : 0u);
    }
    if (flags) rank = atomicAdd(&g_deg[dst], 1);   // rank = within-dst slot

    unsigned ballot = __ballot_sync(0xffffffffu, flags != 0u);
    if (ballot == 0u) return;
    int lane   = threadIdx.x & 31;
    int leader = __ffs(ballot) - 1;
    int base   = 0;
    if (lane == leader) base = atomicAdd(&g_scnt, __popc(ballot));
    base = __shfl_sync(0xffffffffu, base, leader);
    if (flags) {
        int pos = base + __popc(ballot & ((1u << lane) - 1u));
        // src < 2^17 (N=100000); rank fits easily above bit 17.
        g_smeta[pos] = make_uint2((unsigned)src | ((unsigned)rank << 17),
                                  (unsigned)dst | (flags << 30));
        g_sattr[pos] = a;
    }
}

// ---------------------------------------------------------------------------
// CSR build, step 2a: per-1024-block exclusive scan of g_deg into g_off.
// ---------------------------------------------------------------------------
__global__ void k_scan1() {
    __shared__ int warp_tot[32];
    int i    = blockIdx.x * 1024 + threadIdx.x;
    int lane = threadIdx.x & 31;
    int wid  = threadIdx.x >> 5;
    int v = (i < N_NODES) ? g_deg[i] : 0;
    int x = v;
    #pragma unroll
    for (int o = 1; o < 32; o <<= 1) {
        int y = __shfl_up_sync(0xffffffffu, x, o);
        if (lane >= o) x += y;
    }
    if (lane == 31) warp_tot[wid] = x;
    __syncthreads();
    if (wid == 0) {
        int t = warp_tot[lane];
        #pragma unroll
        for (int o = 1; o < 32; o <<= 1) {
            int y = __shfl_up_sync(0xffffffffu, t, o);
            if (lane >= o) t += y;
        }
        warp_tot[lane] = t;
    }
    __syncthreads();
    int incl = x + ((wid > 0) ? warp_tot[wid - 1] : 0);
    if (i < N_NODES) g_off[i] = incl - v;                 // block-local exclusive
    if (threadIdx.x == 1023) g_part[blockIdx.x] = incl;   // block total
}

// Step 2b: parallel exclusive scan of the 98 block totals.
__global__ void k_scan2() {
    __shared__ int wtot[4];
    int i    = threadIdx.x;          // 128 threads
    int lane = i & 31;
    int wid  = i >> 5;
    int v = (i < NB_SCAN) ? g_part[i] : 0;
    int x = v;
    #pragma unroll
    for (int o = 1; o < 32; o <<= 1) {
        int y = __shfl_up_sync(0xffffffffu, x, o);
        if (lane >= o) x += y;
    }
    if (lane == 31) wtot[wid] = x;
    __syncthreads();
    if (i == 0) {
        int r = 0;
        #pragma unroll
        for (int k = 0; k < 4; k++) { int c = wtot[k]; wtot[k] = r; r += c; }
    }
    __syncthreads();
    if (i < NB_SCAN) g_part[i] = x - v + wtot[wid];       // exclusive prefix
}

// ---------------------------------------------------------------------------
// CSR build, step 3: pure arithmetic scatter (no atomics — rank precomputed).
// ---------------------------------------------------------------------------
__global__ void k_place() {
    int r = blockIdx.x * blockDim.x + threadIdx.x;
    if (r >= g_scnt) return;
    uint2  m = g_smeta[r];
    unsigned src  = m.x & 0x1FFFFu;
    unsigned rank = m.x >> 17;
    int dst       = (int)(m.y & 0x3FFFFFFFu);
    unsigned flg  = m.y >> 30;
    int pos = g_off[dst] + g_part[dst >> 10] + (int)rank;
    g_meta[pos] = src | (flg << 30);
    g_attr[pos] = g_sattr[r];
}

// ---------------------------------------------------------------------------
// Fused layer: block-persistent. Edge-MLP weights in registers; edge meta/attr
// staged through per-warp smem; gathers batched 4-wide. Node MLPs run BOTH
// branches in packed f32x2 (FFMA2). LayerNorm uses a joint packed (sum,sumsq)
// butterfly. Register accumulation, no atomics. If last!=0, fused head MLP
// writes d_out. dir==0: read g_hA write g_hB; dir==1: read g_hB write g_hA.
// ---------------------------------------------------------------------------
__global__ void k_layer(int dir, int last,
                        const float* __restrict__ eWs, const float* __restrict__ ebs,
                        const float* __restrict__ eWl, const float* __restrict__ ebl,
                        const float* __restrict__ W1s, const float* __restrict__ b1s,
                        const float* __restrict__ W2s, const float* __restrict__ b2s,
                        const float* __restrict__ W1l, const float* __restrict__ b1l,
                        const float* __restrict__ W2l, const float* __restrict__ b2l,
                        const float* __restrict__ eps_s_p, const float* __restrict__ eps_l_p,
                        const float* __restrict__ ln_g, const float* __restrict__ ln_b,
                        const float* __restrict__ hW1, const float* __restrict__ hb1,
                        const float* __restrict__ hW2, const float* __restrict__ hb2,
                        const float* __restrict__ hW3, const float* __restrict__ hb3,
                        float* __restrict__ out) {
    // Packed (short, long) weight pairs for both node-MLP stages.
    __shared__ __align__(16) unsigned long long s1p[H * H], s2p[H * H];
    __shared__ unsigned long long sb1p[H], sb2p[H];
    __shared__ float sg[H], sb[H];
    __shared__ float sH1[32 * 16], sH2[16 * 8], sH3[8 * 8], sB1[16], sB2[8], sB3[8];
    __shared__ unsigned sEm[NWARP][32];                      // per-warp staged edge meta
    __shared__ float4   sEa[NWARP][32];                      // per-warp staged edge attr
    __shared__ __align__(16) unsigned long long sZp[NWARP][H];  // packed activation staging
    int tid = threadIdx.x;
    for (int i = tid; i < H * H; i += blockDim.x) {
        reinterpret_cast<float2*>(s1p)[i] = make_float2(W1s[i], W1l[i]);
        reinterpret_cast<float2*>(s2p)[i] = make_float2(W2s[i], W2l[i]);
    }
    if (tid < H) {
        reinterpret_cast<float2*>(sb1p)[tid] = make_float2(b1s[tid], b1l[tid]);
        reinterpret_cast<float2*>(sb2p)[tid] = make_float2(b2s[tid], b2l[tid]);
        sg[tid] = ln_g[tid];  sb[tid] = ln_b[tid];
    }
    if (last) {
        for (int i = tid; i < 32 * 16; i += blockDim.x) sH1[i] = hW1[i];
        if (tid < 16 * 8) sH2[tid] = hW2[tid];
        if (tid < 8 * 8)  sH3[tid] = hW3[tid];
        if (tid < 16) sB1[tid] = hb1[tid];
        if (tid < 8)  { sB2[tid] = hb2[tid]; sB3[tid] = hb3[tid]; }
    }
    __syncthreads();

    int lane = tid & 31;
    int wrp  = tid >> 5;

    // Edge-MLP weights: lane-invariant across ALL nodes/edges -> registers.
    float wWs0 = eWs[0 * H + lane], wWs1 = eWs[1 * H + lane];
    float wWs2 = eWs[2 * H + lane], wWs3 = eWs[3 * H + lane];
    float wbs  = ebs[lane];
    float wWl0 = eWl[0 * H + lane], wWl1 = eWl[1 * H + lane];
    float wWl2 = eWl[2 * H + lane], wWl3 = eWl[3 * H + lane];
    float wbl  = ebl[lane];

    int warp0   = (blockIdx.x * blockDim.x + tid) >> 5;
    int n_warps = (NODE_GRID * TBSZ) >> 5;

    const float* __restrict__ h_in  = dir ? g_hB : g_hA;
    float*       __restrict__ h_out = dir ? g_hA : g_hB;

    float eps_s = *eps_s_p;
    float eps_l = *eps_l_p;

    for (int n = warp0; n < N_NODES; n += n_warps) {
        float hv = h_in[n * H + lane];
        float zs = fmaf(eps_s, hv, hv);
        float zl = fmaf(eps_l, hv, hv);

        int start = g_off[n] + g_part[n >> 10];
        int end   = start + g_deg[n];

        // Chunked edge walk: lane i stages edge (base+i)'s meta+attr into
        // per-warp smem (coalesced); consume via broadcast LDS; gathers 4-wide.
        for (int base = start; base < end; base += 32) {
            int cnt = end - base;  if (cnt > 32) cnt = 32;
            if (lane < cnt) {
                int idx = base + lane;
                sEm[wrp][lane] = g_meta[idx];
                sEa[wrp][lane] = g_attr[idx];
            }
            __syncwarp();

            int k = 0;
            for (; k + 4 <= cnt; k += 4) {
                unsigned mk0 = sEm[wrp][k + 0];
                unsigned mk1 = sEm[wrp][k + 1];
                unsigned mk2 = sEm[wrp][k + 2];
                unsigned mk3 = sEm[wrp][k + 3];
                float hs0 = h_in[(int)(mk0 & 0x3FFFFFFFu) * H + lane];
                float hs1 = h_in[(int)(mk1 & 0x3FFFFFFFu) * H + lane];
                float hs2 = h_in[(int)(mk2 & 0x3FFFFFFFu) * H + lane];
                float hs3 = h_in[(int)(mk3 & 0x3FFFFFFFu) * H + lane];

                #pragma unroll
                for (int j = 0; j < 4; j++) {
                    unsigned mk = (j == 0) ? mk0 : (j == 1) ? mk1 : (j == 2) ? mk2 : mk3;
                    float    hs = (j == 0) ? hs0 : (j == 1) ? hs1 : (j == 2) ? hs2 : hs3;
                    float4   a  = sEa[wrp][k + j];
                    unsigned flags = mk >> 30;
                    if (flags & 1u) {
                        float v = hs + wbs;
                        v = fmaf(a.x, wWs0, v);
                        v = fmaf(a.y, wWs1, v);
                        v = fmaf(a.z, wWs2, v);
                        v = fmaf(a.w, wWs3, v);
                        zs += fmaxf(v, 0.f);
                    }
                    if (flags & 2u) {
                        float v = hs + wbl;
                        v = fmaf(a.x, wWl0, v);
                        v = fmaf(a.y, wWl1, v);
                        v = fmaf(a.z, wWl2, v);
                        v = fmaf(a.w, wWl3, v);
                        zl += fmaxf(v, 0.f);
                    }
                }
            }
            for (; k < cnt; k++) {
                unsigned mk = sEm[wrp][k];
                float4   a  = sEa[wrp][k];
                float    hs = h_in[(int)(mk & 0x3FFFFFFFu) * H + lane];
                unsigned flags = mk >> 30;
                if (flags & 1u) {
                    float v = hs + wbs;
                    v = fmaf(a.x, wWs0, v);
                    v = fmaf(a.y, wWs1, v);
                    v = fmaf(a.z, wWs2, v);
                    v = fmaf(a.w, wWs3, v);
                    zs += fmaxf(v, 0.f);
                }
                if (flags & 2u) {
                    float v = hs + wbl;
                    v = fmaf(a.x, wWl0, v);
                    v = fmaf(a.y, wWl1, v);
                    v = fmaf(a.z, wWl2, v);
                    v = fmaf(a.w, wWl3, v);
                    zl += fmaxf(v, 0.f);
                }
            }
            __syncwarp();   // protect staging buffer before next chunk's writes
        }

        // ---- Node MLPs: both branches packed in f32x2 (FFMA2) ----
        sZp[wrp][lane] = pack2(zs, zl);
        __syncwarp();

        unsigned long long acc = sb1p[lane];
        #pragma unroll
        for (int j = 0; j < H; j++) {
            ffma2(acc, sZp[wrp][j], s1p[j * H + lane]);
        }
        float t, u;
        unpack2(acc, t, u);
        t = fmaxf(t, 0.f);
        u = fmaxf(u, 0.f);
        __syncwarp();
        sZp[wrp][lane] = pack2(t, u);
        __syncwarp();

        acc = sb2p[lane];
        #pragma unroll
        for (int j = 0; j < H; j++) {
            ffma2(acc, sZp[wrp][j], s2p[j * H + lane]);
        }
        float os, ol;
        unpack2(acc, os, ol);
        __syncwarp();   // sZp reused next node / below

        // ---- LayerNorm with joint packed (sum, sumsq) butterfly ----
        float v = hv + os + ol;
        unsigned long long pr = warp_sum2(pack2(v, v * v));
        float s1, s2;
        unpack2(pr, s1, s2);
        float mu  = s1 * (1.f / H);
        float var = fmaf(-mu, mu, s2 * (1.f / H));
        float y   = (v - mu) * rsqrtf(var + 1e-5f) * sg[lane] + sb[lane];
        float hr  = fmaxf(y, 0.f);

        if (!last) {
            h_out[n * H + lane] = hr;
            continue;
        }

        // Fused head via float view of the packed staging (64 floats/warp):
        // hr in [0..31], t1 in [32..47], t2 in [48..55]; all float4-aligned.
        float* sZf = reinterpret_cast<float*>(sZp[wrp]);
        sZf[lane] = hr;
        __syncwarp();
        int l16 = lane & 15;
        float t1 = sB1[l16];
        #pragma unroll
        for (int j = 0; j < 32; j += 4) {
            float4 h4 = *reinterpret_cast<const float4*>(&sZf[j]);
            t1 = fmaf(h4.x, sH1[(j + 0) * 16 + l16], t1);
            t1 = fmaf(h4.y, sH1[(j + 1) * 16 + l16], t1);
            t1 = fmaf(h4.z, sH1[(j + 2) * 16 + l16], t1);
            t1 = fmaf(h4.w, sH1[(j + 3) * 16 + l16], t1);
        }
        t1 = fmaxf(t1, 0.f);   // lanes 16..31 duplicate lanes 0..15
        __syncwarp();
        if (lane < 16) sZf[32 + lane] = t1;
        __syncwarp();

        int l8 = lane & 7;
        float t2 = sB2[l8];
        #pragma unroll
        for (int j = 0; j < 16; j += 4) {
            float4 t4 = *reinterpret_cast<const float4*>(&sZf[32 + j]);
            t2 = fmaf(t4.x, sH2[(j + 0) * 8 + l8], t2);
            t2 = fmaf(t4.y, sH2[(j + 1) * 8 + l8], t2);
            t2 = fmaf(t4.z, sH2[(j + 2) * 8 + l8], t2);
            t2 = fmaf(t4.w, sH2[(j + 3) * 8 + l8], t2);
        }
        t2 = fmaxf(t2, 0.f);   // lanes 8..31 duplicate lanes 0..7
        __syncwarp();
        if (lane < 8) sZf[48 + lane] = t2;
        __syncwarp();

        float o = sB3[l8];
        #pragma unroll
        for (int j = 0; j < 8; j += 4) {
            float4 t4 = *reinterpret_cast<const float4*>(&sZf[48 + j]);
            o = fmaf(t4.x, sH3[(j + 0) * 8 + l8], o);
            o = fmaf(t4.y, sH3[(j + 1) * 8 + l8], o);
            o = fmaf(t4.z, sH3[(j + 2) * 8 + l8], o);
            o = fmaf(t4.w, sH3[(j + 3) * 8 + l8], o);
        }
        __syncwarp();   // sZp reused next node

        if (lane < 8) out[n * 8 + lane] = o;
    }
}

// ---------------------------------------------------------------------------
// Launch (7 kernels total)
// ---------------------------------------------------------------------------
extern "C" void kernel_launch(void* const* d_in, const int* in_sizes, int n_in,
                              void* d_out, int out_size) {
    const int*   aa_idx    = (const int*)  d_in[0];
    const int*   atom_idx  = (const int*)  d_in[1];
    const int*   edge_idx  = (const int*)  d_in[2];
    const float* edge_attr = (const float*)d_in[3];
    const float* aa_emb    = (const float*)d_in[4];
    const float* atom_emb  = (const float*)d_in[5];
    const float* proj_W1   = (const float*)d_in[6];
    const float* proj_b1   = (const float*)d_in[7];
    const float* proj_W2   = (const float*)d_in[8];
    const float* proj_b2   = (const float*)d_in[9];
    const float* short_eps = (const float*)d_in[10];
    const float* short_eW  = (const float*)d_in[11];
    const float* short_eb  = (const float*)d_in[12];
    const float* short_W1  = (const float*)d_in[13];
    const float* short_b1  = (const float*)d_in[14];
    const float* short_W2  = (const float*)d_in[15];
    const float* short_b2  = (const float*)d_in[16];
    const float* long_eps  = (const float*)d_in[17];
    const float* long_eW   = (const float*)d_in[18];
    const float* long_eb   = (const float*)d_in[19];
    const float* long_W1   = (const float*)d_in[20];
    const float* long_b1   = (const float*)d_in[21];
    const float* long_W2   = (const float*)d_in[22];
    const float* long_b2   = (const float*)d_in[23];
    const float* ln_g      = (const float*)d_in[24];
    const float* ln_b      = (const float*)d_in[25];
    const float* head_W1   = (const float*)d_in[26];
    const float* head_b1   = (const float*)d_in[27];
    const float* head_W2   = (const float*)d_in[28];
    const float* head_b2   = (const float*)d_in[29];
    const float* head_W3   = (const float*)d_in[30];
    const float* head_b3   = (const float*)d_in[31];
    float* out = (float*)d_out;

    const int edge_blocks = (N_EDGES + TBSZ - 1) / TBSZ;

    k_init<<<NODE_GRID, TBSZ>>>(aa_idx, atom_idx, aa_emb, atom_emb,
                                proj_W1, proj_b1, proj_W2, proj_b2);

    // One-time CSR build (masks are layer-invariant).
    k_hist<<<edge_blocks, TBSZ>>>(edge_idx, edge_attr, atom_idx);
    k_scan1<<<NB_SCAN, 1024>>>();
    k_scan2<<<1, 128>>>();
    k_place<<<edge_blocks, TBSZ>>>();

    for (int l = 0; l < 2; l++) {
        k_layer<<<NODE_GRID, TBSZ>>>(l, (l == 1) ? 1 : 0,
            short_eW + l * 4 * H, short_eb + l * H,
            long_eW  + l * 4 * H, long_eb  + l * H,
            short_W1 + l * H * H, short_b1 + l * H,
            short_W2 + l * H * H, short_b2 + l * H,
            long_W1  + l * H * H, long_b1  + l * H,
            long_W2  + l * H * H, long_b2  + l * H,
            short_eps + l, long_eps + l,
            ln_g + l * H, ln_b + l * H,
            head_W1, head_b1, head_W2, head_b2, head_W3, head_b3, out);
    }
}